// round 1
// baseline (speedup 1.0000x reference)
#include <cuda_runtime.h>

#define NP 1000000
#define NPIL 30000

// ---------------- scratch (static device globals; no allocation) ----------------
__device__ float d_W1f[7 * 32];          // W1 with BN1 scale folded in
__device__ float d_t1[32];               // BN1 shift
__device__ float d_W2f[64 * 32];         // W2 with BN2 scale folded in
__device__ float d_t2[32];               // BN2 shift
__device__ int   d_count[NPIL];
__device__ int   d_cursor[NPIL];
__device__ int   d_offset[NPIL + 1];
__device__ __align__(16) float d_hs[(size_t)NP * 32];   // pillar-sorted h rows (128 MB)

// ---------------- fold BN into weights ----------------
__global__ void k_fold(const float* __restrict__ W1, const float* __restrict__ g1,
                       const float* __restrict__ b1, const float* __restrict__ m1,
                       const float* __restrict__ v1, const float* __restrict__ W2,
                       const float* __restrict__ g2, const float* __restrict__ b2,
                       const float* __restrict__ m2, const float* __restrict__ v2) {
    int j = threadIdx.x;
    if (j >= 32) return;
    float s1 = g1[j] * rsqrtf(v1[j] + 1e-3f);
    d_t1[j] = b1[j] - m1[j] * s1;
    for (int k = 0; k < 7; k++) d_W1f[k * 32 + j] = W1[k * 32 + j] * s1;
    float s2 = g2[j] * rsqrtf(v2[j] + 1e-3f);
    d_t2[j] = b2[j] - m2[j] * s2;
    for (int k = 0; k < 64; k++) d_W2f[k * 32 + j] = W2[k * 32 + j] * s2;
}

// ---------------- zero per-launch state ----------------
__global__ void k_zero() {
    int i = blockIdx.x * blockDim.x + threadIdx.x;
    if (i < NPIL) { d_count[i] = 0; d_cursor[i] = 0; }
}

// ---------------- histogram of pillar ids ----------------
__global__ void k_hist(const int* __restrict__ unq) {
    int i = blockIdx.x * blockDim.x + threadIdx.x;
    if (i < NP) atomicAdd(&d_count[unq[i]], 1);
}

// ---------------- single-block exclusive scan of counts ----------------
__global__ void k_scan() {
    __shared__ int sh[1024];
    const int CH = 30;                 // 1024*30 = 30720 >= 30000
    int t = threadIdx.x;
    int base = t * CH;
    int s = 0;
    for (int e = 0; e < CH; e++) {
        int idx = base + e;
        if (idx < NPIL) s += d_count[idx];
    }
    sh[t] = s;
    __syncthreads();
    for (int d = 1; d < 1024; d <<= 1) {
        int v = (t >= d) ? sh[t - d] : 0;
        __syncthreads();
        sh[t] += v;
        __syncthreads();
    }
    int run = (t > 0) ? sh[t - 1] : 0;
    for (int e = 0; e < CH; e++) {
        int idx = base + e;
        if (idx < NPIL) { d_offset[idx] = run; run += d_count[idx]; }
    }
    if (t == 1023) d_offset[NPIL] = sh[1023];
}

// ---------------- pass 1: compute h, scatter into pillar-sorted layout ----------------
__global__ __launch_bounds__(256) void k_pass1(const float* __restrict__ pts,
                                               const float* __restrict__ fc,
                                               const int* __restrict__ unq) {
    __shared__ float sw[7 * 32];
    __shared__ float st[32];
    int t = threadIdx.x;
    if (t < 224) sw[t] = d_W1f[t];
    if (t < 32) st[t] = d_t1[t];
    __syncthreads();

    int i = blockIdx.x * 256 + t;
    if (i >= NP) return;

    float f[7];
    f[0] = fc[i * 3 + 0];
    f[1] = fc[i * 3 + 1];
    f[2] = fc[i * 3 + 2];
    f[3] = pts[i * 5 + 1];
    f[4] = pts[i * 5 + 2];
    f[5] = pts[i * 5 + 3];
    f[6] = pts[i * 5 + 4];

    float h[32];
#pragma unroll
    for (int j = 0; j < 32; j++) h[j] = st[j];
#pragma unroll
    for (int k = 0; k < 7; k++) {
        float fk = f[k];
#pragma unroll
        for (int j = 0; j < 32; j++) h[j] = fmaf(fk, sw[k * 32 + j], h[j]);
    }

    int p = unq[i];
    int pos = d_offset[p] + atomicAdd(&d_cursor[p], 1);
    float4* dst = reinterpret_cast<float4*>(&d_hs[(size_t)pos * 32]);
#pragma unroll
    for (int q = 0; q < 8; q++) {
        float4 v;
        v.x = fmaxf(h[q * 4 + 0], 0.f);
        v.y = fmaxf(h[q * 4 + 1], 0.f);
        v.z = fmaxf(h[q * 4 + 2], 0.f);
        v.w = fmaxf(h[q * 4 + 3], 0.f);
        dst[q] = v;
    }
}

// ---------------- pass 2: warp per pillar: mean -> pm, then out rows -> max ----------------
__global__ __launch_bounds__(256) void k_pillar(float* __restrict__ out) {
    __shared__ float buf[8][32];
    int warp = threadIdx.x >> 5;
    int j = threadIdx.x & 31;
    int p = blockIdx.x * 8 + warp;
    if (p >= NPIL) return;

    // register-resident columns of W2a / W2b for lane j
    float w2a[32], w2b[32];
#pragma unroll
    for (int k = 0; k < 32; k++) {
        w2a[k] = d_W2f[k * 32 + j];
        w2b[k] = d_W2f[(k + 32) * 32 + j];
    }
    float t2j = d_t2[j];

    int off = d_offset[p];
    int cnt = d_offset[p + 1] - off;

    // sweep 1: channel-wise sum over the segment (coalesced 128B rows)
    float s0 = 0.f, s1 = 0.f, s2 = 0.f, s3 = 0.f;
    int r = 0;
    for (; r + 4 <= cnt; r += 4) {
        s0 += d_hs[(size_t)(off + r + 0) * 32 + j];
        s1 += d_hs[(size_t)(off + r + 1) * 32 + j];
        s2 += d_hs[(size_t)(off + r + 2) * 32 + j];
        s3 += d_hs[(size_t)(off + r + 3) * 32 + j];
    }
    for (; r < cnt; r++) s0 += d_hs[(size_t)(off + r) * 32 + j];
    float sum = (s0 + s1) + (s2 + s3);
    float mean = (cnt > 0) ? sum / (float)cnt : 0.f;

    // pm_j = t2_j + mean . W2b[:,j]
    buf[warp][j] = mean;
    __syncwarp();
    float pm = t2j;
#pragma unroll
    for (int k = 0; k < 32; k++) pm = fmaf(buf[warp][k], w2b[k], pm);
    __syncwarp();

    // sweep 2: out_r = h_r @ W2a + pm, reduce max (ReLU folded into max-with-0 init)
    float maxv = 0.f;
    float hj = (cnt > 0) ? d_hs[(size_t)off * 32 + j] : 0.f;
    for (int rr = 0; rr < cnt; rr++) {
        buf[warp][j] = hj;
        __syncwarp();
        float hn = (rr + 1 < cnt) ? d_hs[(size_t)(off + rr + 1) * 32 + j] : 0.f;
        float a0 = 0.f, a1 = 0.f, a2 = 0.f, a3 = 0.f;
#pragma unroll
        for (int k = 0; k < 32; k += 4) {
            a0 = fmaf(buf[warp][k + 0], w2a[k + 0], a0);
            a1 = fmaf(buf[warp][k + 1], w2a[k + 1], a1);
            a2 = fmaf(buf[warp][k + 2], w2a[k + 2], a2);
            a3 = fmaf(buf[warp][k + 3], w2a[k + 3], a3);
        }
        __syncwarp();
        float acc = pm + ((a0 + a1) + (a2 + a3));
        maxv = fmaxf(maxv, acc);
        hj = hn;
    }
    out[p * 32 + j] = maxv;
}

// ---------------- launch ----------------
extern "C" void kernel_launch(void* const* d_in, const int* in_sizes, int n_in,
                              void* d_out, int out_size) {
    const float* points   = (const float*)d_in[0];
    const float* f_center = (const float*)d_in[1];
    const int*   unq      = (const int*)d_in[2];
    const float* W1 = (const float*)d_in[3];
    const float* g1 = (const float*)d_in[4];
    const float* b1 = (const float*)d_in[5];
    const float* m1 = (const float*)d_in[6];
    const float* v1 = (const float*)d_in[7];
    const float* W2 = (const float*)d_in[8];
    const float* g2 = (const float*)d_in[9];
    const float* b2 = (const float*)d_in[10];
    const float* m2 = (const float*)d_in[11];
    const float* v2 = (const float*)d_in[12];

    k_fold<<<1, 32>>>(W1, g1, b1, m1, v1, W2, g2, b2, m2, v2);
    k_zero<<<(NPIL + 255) / 256, 256>>>();
    k_hist<<<(NP + 255) / 256, 256>>>(unq);
    k_scan<<<1, 1024>>>();
    k_pass1<<<(NP + 255) / 256, 256>>>(points, f_center, unq);
    k_pillar<<<NPIL / 8, 256>>>((float*)d_out);
}

// round 3
// speedup vs baseline: 1.2203x; 1.2203x over previous
#include <cuda_runtime.h>

#define NP 1000000
#define NPIL 30000

typedef unsigned long long ull;

__device__ __forceinline__ ull pack2(float lo, float hi) {
    ull r; asm("mov.b64 %0,{%1,%2};" : "=l"(r) : "f"(lo), "f"(hi)); return r;
}
__device__ __forceinline__ void unpack2(ull v, float& lo, float& hi) {
    asm("mov.b64 {%0,%1},%2;" : "=f"(lo), "=f"(hi) : "l"(v));
}
__device__ __forceinline__ ull ffma2(ull a, ull b, ull c) {
    ull d; asm("fma.rn.f32x2 %0,%1,%2,%3;" : "=l"(d) : "l"(a), "l"(b), "l"(c)); return d;
}
__device__ __forceinline__ ull fadd2(ull a, ull b) {
    ull d; asm("add.rn.f32x2 %0,%1,%2;" : "=l"(d) : "l"(a), "l"(b)); return d;
}

// ---------------- scratch ----------------
__device__ float d_W1f[7 * 32];
__device__ float d_t1[32];
__device__ float d_W2f[64 * 32];
__device__ float d_t2[32];
__device__ int   d_count[NPIL];
__device__ int   d_cursor[NPIL];
__device__ int   d_offset[NPIL];
__device__ int   d_galloc;
__device__ __align__(16) float d_hs[(size_t)NP * 32];   // pillar-grouped h rows (128 MB)

// ---------------- init: zero counters + fold BN into weights ----------------
__global__ void k_init(const float* __restrict__ W1, const float* __restrict__ g1,
                       const float* __restrict__ b1, const float* __restrict__ m1,
                       const float* __restrict__ v1, const float* __restrict__ W2,
                       const float* __restrict__ g2, const float* __restrict__ b2,
                       const float* __restrict__ m2, const float* __restrict__ v2) {
    int i = blockIdx.x * blockDim.x + threadIdx.x;
    if (i < NPIL) { d_count[i] = 0; d_cursor[i] = 0; }
    if (i == 0) d_galloc = 0;
    if (blockIdx.x == 0 && threadIdx.x < 32) {
        int j = threadIdx.x;
        float s1 = g1[j] * rsqrtf(v1[j] + 1e-3f);
        d_t1[j] = b1[j] - m1[j] * s1;
        for (int k = 0; k < 7; k++) d_W1f[k * 32 + j] = W1[k * 32 + j] * s1;
        float s2 = g2[j] * rsqrtf(v2[j] + 1e-3f);
        d_t2[j] = b2[j] - m2[j] * s2;
        for (int k = 0; k < 64; k++) d_W2f[k * 32 + j] = W2[k * 32 + j] * s2;
    }
}

// ---------------- histogram (int4 vectorized) ----------------
__global__ void k_hist(const int* __restrict__ unq) {
    int i = blockIdx.x * blockDim.x + threadIdx.x;
    if (i < NP / 4) {
        int4 v = ((const int4*)unq)[i];
        atomicAdd(&d_count[v.x], 1);
        atomicAdd(&d_count[v.y], 1);
        atomicAdd(&d_count[v.z], 1);
        atomicAdd(&d_count[v.w], 1);
    }
}

// ---------------- segment allocation: block scan + one global atomic per block ----------------
// Offsets need not be monotonic across pillars — only disjoint & contiguous per pillar.
__global__ __launch_bounds__(256) void k_alloc() {
    __shared__ int wsum[8], wpre[8], sbase;
    int t = threadIdx.x, lane = t & 31, w = t >> 5;
    int i = blockIdx.x * 256 + t;
    int c = (i < NPIL) ? d_count[i] : 0;
    int incl = c;
#pragma unroll
    for (int d = 1; d < 32; d <<= 1) {
        int v = __shfl_up_sync(0xffffffffu, incl, d);
        if (lane >= d) incl += v;
    }
    if (lane == 31) wsum[w] = incl;
    __syncthreads();
    if (w == 0 && lane < 8) {
        int s = wsum[lane];
        int inc = s;
#pragma unroll
        for (int d = 1; d < 8; d <<= 1) {
            int v = __shfl_up_sync(0xffu, inc, d);
            if (lane >= d) inc += v;
        }
        wpre[lane] = inc - s;
        if (lane == 7) sbase = atomicAdd(&d_galloc, inc);
    }
    __syncthreads();
    if (i < NPIL) d_offset[i] = sbase + wpre[w] + (incl - c);
}

// ---------------- pass 1: h = relu(feat @ W1f + t1), scatter to pillar-grouped rows ----------------
__global__ __launch_bounds__(256) void k_pass1(const float* __restrict__ pts,
                                               const float* __restrict__ fc,
                                               const int* __restrict__ unq) {
    __shared__ ull swp[112];   // 7 x 16 packed weight pairs
    __shared__ ull st2[16];
    int t = threadIdx.x;
    if (t < 112) { float2 w = ((const float2*)d_W1f)[t]; swp[t] = pack2(w.x, w.y); }
    if (t < 16)  { float2 v = ((const float2*)d_t1)[t];  st2[t] = pack2(v.x, v.y); }
    __syncthreads();

    int i = blockIdx.x * 256 + t;
    if (i >= NP) return;

    float f[7];
    f[0] = fc[i * 3 + 0];
    f[1] = fc[i * 3 + 1];
    f[2] = fc[i * 3 + 2];
    f[3] = pts[i * 5 + 1];
    f[4] = pts[i * 5 + 2];
    f[5] = pts[i * 5 + 3];
    f[6] = pts[i * 5 + 4];

    ull h2[16];
#pragma unroll
    for (int j = 0; j < 16; j++) h2[j] = st2[j];
#pragma unroll
    for (int k = 0; k < 7; k++) {
        ull fk = pack2(f[k], f[k]);
#pragma unroll
        for (int j = 0; j < 16; j++) h2[j] = ffma2(swp[k * 16 + j], fk, h2[j]);
    }

    int p = unq[i];
    int pos = d_offset[p] + atomicAdd(&d_cursor[p], 1);
    float4* dst = reinterpret_cast<float4*>(&d_hs[(size_t)pos * 32]);
#pragma unroll
    for (int q = 0; q < 8; q++) {
        float x0, x1, x2, x3;
        unpack2(h2[q * 2 + 0], x0, x1);
        unpack2(h2[q * 2 + 1], x2, x3);
        float4 v;
        v.x = fmaxf(x0, 0.f); v.y = fmaxf(x1, 0.f);
        v.z = fmaxf(x2, 0.f); v.w = fmaxf(x3, 0.f);
        dst[q] = v;
    }
}

// ---------------- pass 2: warp/pillar: mean -> pm, then f32x2 row-pair GEMV + max ----------------
__global__ __launch_bounds__(256) void k_pillar(float* __restrict__ out) {
    __shared__ float sW[64 * 32];                  // folded W2 (8 KB)
    __shared__ __align__(16) ull sh[8][32];        // packed row-pairs per warp
    __shared__ float shm[8][32];                   // per-warp mean broadcast

    for (int q = threadIdx.x; q < 2048; q += 256) sW[q] = d_W2f[q];
    __syncthreads();

    int warp = threadIdx.x >> 5;
    int j = threadIdx.x & 31;
    int p = blockIdx.x * 8 + warp;
    if (p >= NPIL) return;

    int off = d_offset[p];
    int cnt = d_count[p];
    if (cnt == 0) { out[p * 32 + j] = 0.f; return; }

    const float* base = &d_hs[(size_t)off * 32 + j];

    // sweep 1: channel sums (coalesced 128B rows, unroll-4 for MLP)
    float s0 = 0.f, s1 = 0.f, s2 = 0.f, s3 = 0.f;
    int r = 0;
    for (; r + 4 <= cnt; r += 4) {
        s0 += base[(r + 0) * 32];
        s1 += base[(r + 1) * 32];
        s2 += base[(r + 2) * 32];
        s3 += base[(r + 3) * 32];
    }
    for (; r < cnt; r++) s0 += base[r * 32];
    float mean = ((s0 + s1) + (s2 + s3)) / (float)cnt;

    // pm_j = t2_j + mean . W2b[:,j]
    shm[warp][j] = mean;
    __syncwarp();
    float pm = d_t2[j];
#pragma unroll
    for (int k = 0; k < 32; k++) pm = fmaf(shm[warp][k], sW[(k + 32) * 32 + j], pm);
    __syncwarp();

    // pre-pack W2a columns as {w,w} pairs
    ull w2ap[32];
#pragma unroll
    for (int k = 0; k < 32; k++) {
        float w = sW[k * 32 + j];
        w2ap[k] = pack2(w, w);
    }
    ull pm2 = pack2(pm, pm);
    ull z2 = pack2(0.f, 0.f);

    // sweep 2: two rows per iteration via fma.rn.f32x2; odd tail duplicates last row
    float maxv = 0.f;
    const ull* row = sh[warp];
    for (int r2 = 0; r2 < cnt; r2 += 2) {
        int rb = (r2 + 1 < cnt) ? (r2 + 1) : r2;
        float a0 = base[r2 * 32];
        float a1 = base[rb * 32];
        sh[warp][j] = pack2(a0, a1);
        __syncwarp();
        ull acc0 = pm2, acc1 = z2, acc2 = z2, acc3 = z2;
#pragma unroll
        for (int k = 0; k < 32; k += 4) {
            ulonglong2 v01 = *reinterpret_cast<const ulonglong2*>(&row[k]);
            ulonglong2 v23 = *reinterpret_cast<const ulonglong2*>(&row[k + 2]);
            acc0 = ffma2(v01.x, w2ap[k + 0], acc0);
            acc1 = ffma2(v01.y, w2ap[k + 1], acc1);
            acc2 = ffma2(v23.x, w2ap[k + 2], acc2);
            acc3 = ffma2(v23.y, w2ap[k + 3], acc3);
        }
        __syncwarp();
        ull tt = fadd2(fadd2(acc0, acc1), fadd2(acc2, acc3));
        float lo, hi;
        unpack2(tt, lo, hi);
        maxv = fmaxf(maxv, fmaxf(lo, hi));
    }
    out[p * 32 + j] = maxv;
}

// ---------------- launch ----------------
extern "C" void kernel_launch(void* const* d_in, const int* in_sizes, int n_in,
                              void* d_out, int out_size) {
    const float* points   = (const float*)d_in[0];
    const float* f_center = (const float*)d_in[1];
    const int*   unq      = (const int*)d_in[2];
    const float* W1 = (const float*)d_in[3];
    const float* g1 = (const float*)d_in[4];
    const float* b1 = (const float*)d_in[5];
    const float* m1 = (const float*)d_in[6];
    const float* v1 = (const float*)d_in[7];
    const float* W2 = (const float*)d_in[8];
    const float* g2 = (const float*)d_in[9];
    const float* b2 = (const float*)d_in[10];
    const float* m2 = (const float*)d_in[11];
    const float* v2 = (const float*)d_in[12];

    k_init<<<(NPIL + 255) / 256, 256>>>(W1, g1, b1, m1, v1, W2, g2, b2, m2, v2);
    k_hist<<<(NP / 4 + 255) / 256, 256>>>(unq);
    k_alloc<<<(NPIL + 255) / 256, 256>>>();
    k_pass1<<<(NP + 255) / 256, 256>>>(points, f_center, unq);
    k_pillar<<<NPIL / 8, 256>>>((float*)d_out);
}